// round 1
// baseline (speedup 1.0000x reference)
#include <cuda_runtime.h>
#include <cstddef>

// Problem constants
#define B_   4
#define N_   4096
#define E_   256
#define F_   256      // F_IN == F_OUT
#define MAXE 50
#define H1_  128
#define H2_  64
#define OUTC 512      // E_ + F_OUT

// ---------------------------------------------------------------------------
// Static device scratch (no dynamic allocation allowed)
// ---------------------------------------------------------------------------
__device__ float g_xp[B_ * N_ * F_];          // x @ Wn_w + Wn_b        (16 MB)
__device__ float g_v [B_ * N_ * F_];          // x @ weight             (16 MB)
__device__ float g_S [67108864];              // [B][4096][4096] scores (256 MB)
__device__ float g_mean[B_ * MAXE * F_];      // per-edge mean features
__device__ float g_ctx [B_ * MAXE];           // MLP context scalar per (b,e)
__device__ float g_deg [MAXE];                // edge degrees (float)

// ---------------------------------------------------------------------------
// SGEMM config: 128x128 tile, BK=8, 8x8 per thread, 256 threads
// All dims used are multiples of the tile sizes -> no bounds checks.
// ---------------------------------------------------------------------------
#define BM 128
#define BN 128
#define BK 8
#define TM 8
#define TN 8

// C[z] = A[z](MxK) * B[z](KxN) * scale + bias  (B row-major, bias may be null)
__global__ __launch_bounds__(256)
void sgemm_nn(const float* __restrict__ A, const float* __restrict__ Bm,
              const float* __restrict__ bias, float* __restrict__ C,
              int M, int N, int K, int lda, int ldb, int ldc,
              size_t sA, size_t sB, size_t sC, float scale)
{
    __shared__ float As[BK][BM];
    __shared__ float Bs[BK][BN];
    const int tid = threadIdx.x;

    A  += (size_t)blockIdx.z * sA + (size_t)blockIdx.y * BM * lda;
    Bm += (size_t)blockIdx.z * sB + (size_t)blockIdx.x * BN;
    C  += (size_t)blockIdx.z * sC + (size_t)blockIdx.y * BM * ldc
        + (size_t)blockIdx.x * BN;

    const int arow = tid >> 1, acol = (tid & 1) << 2;   // A tile: 128 x 8
    const int brow = tid >> 5, bcol = (tid & 31) << 2;  // B tile: 8 x 128
    const int trow = (tid >> 4) * TM;
    const int tcol = (tid & 15) * TN;

    float acc[TM][TN];
#pragma unroll
    for (int i = 0; i < TM; i++)
#pragma unroll
        for (int j = 0; j < TN; j++) acc[i][j] = 0.f;

    for (int k0 = 0; k0 < K; k0 += BK) {
        float4 a = *(const float4*)(A + (size_t)arow * lda + k0 + acol);
        As[acol + 0][arow] = a.x;
        As[acol + 1][arow] = a.y;
        As[acol + 2][arow] = a.z;
        As[acol + 3][arow] = a.w;
        float4 b = *(const float4*)(Bm + (size_t)(k0 + brow) * ldb + bcol);
        *(float4*)&Bs[brow][bcol] = b;
        __syncthreads();
#pragma unroll
        for (int kk = 0; kk < BK; kk++) {
            float ra[TM], rb[TN];
            *(float4*)&ra[0] = *(const float4*)&As[kk][trow];
            *(float4*)&ra[4] = *(const float4*)&As[kk][trow + 4];
            *(float4*)&rb[0] = *(const float4*)&Bs[kk][tcol];
            *(float4*)&rb[4] = *(const float4*)&Bs[kk][tcol + 4];
#pragma unroll
            for (int i = 0; i < TM; i++)
#pragma unroll
                for (int j = 0; j < TN; j++)
                    acc[i][j] = fmaf(ra[i], rb[j], acc[i][j]);
        }
        __syncthreads();
    }

#pragma unroll
    for (int i = 0; i < TM; i++) {
        float o[TN];
#pragma unroll
        for (int j = 0; j < TN; j++) {
            o[j] = acc[i][j] * scale;
            if (bias) o[j] += bias[(size_t)blockIdx.x * BN + tcol + j];
        }
        float* Cr = C + (size_t)(trow + i) * ldc + tcol;
        *(float4*)Cr       = *(float4*)&o[0];
        *(float4*)(Cr + 4) = *(float4*)&o[4];
    }
}

// C[z] = A[z](MxK) * B[z](NxK)^T * scale
__global__ __launch_bounds__(256)
void sgemm_nt(const float* __restrict__ A, const float* __restrict__ Bm,
              float* __restrict__ C,
              int M, int N, int K, int lda, int ldb, int ldc,
              size_t sA, size_t sB, size_t sC, float scale)
{
    __shared__ float As[BK][BM];
    __shared__ float Bs[BK][BN];
    const int tid = threadIdx.x;

    A  += (size_t)blockIdx.z * sA + (size_t)blockIdx.y * BM * lda;
    Bm += (size_t)blockIdx.z * sB + (size_t)blockIdx.x * BN * ldb;
    C  += (size_t)blockIdx.z * sC + (size_t)blockIdx.y * BM * ldc
        + (size_t)blockIdx.x * BN;

    const int arow = tid >> 1, acol = (tid & 1) << 2;
    const int trow = (tid >> 4) * TM;
    const int tcol = (tid & 15) * TN;

    float acc[TM][TN];
#pragma unroll
    for (int i = 0; i < TM; i++)
#pragma unroll
        for (int j = 0; j < TN; j++) acc[i][j] = 0.f;

    for (int k0 = 0; k0 < K; k0 += BK) {
        float4 a = *(const float4*)(A + (size_t)arow * lda + k0 + acol);
        As[acol + 0][arow] = a.x;
        As[acol + 1][arow] = a.y;
        As[acol + 2][arow] = a.z;
        As[acol + 3][arow] = a.w;
        float4 b = *(const float4*)(Bm + (size_t)arow * ldb + k0 + acol);
        Bs[acol + 0][arow] = b.x;
        Bs[acol + 1][arow] = b.y;
        Bs[acol + 2][arow] = b.z;
        Bs[acol + 3][arow] = b.w;
        __syncthreads();
#pragma unroll
        for (int kk = 0; kk < BK; kk++) {
            float ra[TM], rb[TN];
            *(float4*)&ra[0] = *(const float4*)&As[kk][trow];
            *(float4*)&ra[4] = *(const float4*)&As[kk][trow + 4];
            *(float4*)&rb[0] = *(const float4*)&Bs[kk][tcol];
            *(float4*)&rb[4] = *(const float4*)&Bs[kk][tcol + 4];
#pragma unroll
            for (int i = 0; i < TM; i++)
#pragma unroll
                for (int j = 0; j < TN; j++)
                    acc[i][j] = fmaf(ra[i], rb[j], acc[i][j]);
        }
        __syncthreads();
    }

#pragma unroll
    for (int i = 0; i < TM; i++) {
        float o[TN];
#pragma unroll
        for (int j = 0; j < TN; j++) o[j] = acc[i][j] * scale;
        float* Cr = C + (size_t)(trow + i) * ldc + tcol;
        *(float4*)Cr       = *(float4*)&o[0];
        *(float4*)(Cr + 4) = *(float4*)&o[4];
    }
}

// ---------------------------------------------------------------------------
// Row softmax in place on g_S.  grid (4096, 1, B), 256 threads.
// ---------------------------------------------------------------------------
__global__ __launch_bounds__(256)
void softmax_rows(float* __restrict__ S)
{
    float* row = S + ((size_t)blockIdx.z * N_ + blockIdx.x) * N_;
    float4* row4 = (float4*)row;
    const int tid = threadIdx.x;
    const int lane = tid & 31, wid = tid >> 5;
    __shared__ float redm[8];
    __shared__ float reds[8];
    __shared__ float bval;

    float4 r[4];
    float mx = -1e30f;
#pragma unroll
    for (int k = 0; k < 4; k++) {
        r[k] = row4[tid + k * 256];
        mx = fmaxf(mx, fmaxf(fmaxf(r[k].x, r[k].y), fmaxf(r[k].z, r[k].w)));
    }
#pragma unroll
    for (int off = 16; off; off >>= 1)
        mx = fmaxf(mx, __shfl_xor_sync(0xffffffffu, mx, off));
    if (lane == 0) redm[wid] = mx;
    __syncthreads();
    if (tid == 0) {
        float m = redm[0];
#pragma unroll
        for (int i = 1; i < 8; i++) m = fmaxf(m, redm[i]);
        bval = m;
    }
    __syncthreads();
    mx = bval;

    float s = 0.f;
#pragma unroll
    for (int k = 0; k < 4; k++) {
        r[k].x = __expf(r[k].x - mx); s += r[k].x;
        r[k].y = __expf(r[k].y - mx); s += r[k].y;
        r[k].z = __expf(r[k].z - mx); s += r[k].z;
        r[k].w = __expf(r[k].w - mx); s += r[k].w;
    }
#pragma unroll
    for (int off = 16; off; off >>= 1)
        s += __shfl_xor_sync(0xffffffffu, s, off);
    if (lane == 0) reds[wid] = s;
    __syncthreads();
    if (tid == 0) {
        float t = 0.f;
#pragma unroll
        for (int i = 0; i < 8; i++) t += reds[i];
        bval = 1.f / t;
    }
    __syncthreads();
    const float inv = bval;
#pragma unroll
    for (int k = 0; k < 4; k++) {
        r[k].x *= inv; r[k].y *= inv; r[k].z *= inv; r[k].w *= inv;
        row4[tid + k * 256] = r[k];
    }
}

// ---------------------------------------------------------------------------
// Hyperedge branch
// ---------------------------------------------------------------------------
// grid (MAXE, B), 256 threads: per-edge degree + mean feature vector
__global__ __launch_bounds__(256)
void edge_mean_kernel(const float* __restrict__ x, const int* __restrict__ Hm)
{
    const int e = blockIdx.x, b = blockIdx.y, f = threadIdx.x;
    const float* xb = x + (size_t)b * N_ * F_;
    float sum = 0.f;
    int cnt = 0;
    for (int n = 0; n < N_; n++) {
        if (Hm[(size_t)n * E_ + e]) {
            sum += xb[(size_t)n * F_ + f];
            cnt++;
        }
    }
    const float deg = (float)cnt;
    g_mean[((size_t)b * MAXE + e) * F_ + f] = sum / fmaxf(deg, 1.0f);
    if (f == 0 && b == 0) g_deg[e] = deg;
}

// grid (MAXE, B), 128 threads: 256->128->64->1 MLP on mean features
__global__ __launch_bounds__(128)
void ctx_kernel(const float* __restrict__ m1w, const float* __restrict__ m1b,
                const float* __restrict__ m2w, const float* __restrict__ m2b,
                const float* __restrict__ m3w, const float* __restrict__ m3b)
{
    const int e = blockIdx.x, b = blockIdx.y, t = threadIdx.x;
    __shared__ float ms[F_];
    __shared__ float h1[H1_];
    __shared__ float h2[H2_];
    __shared__ float red[4];

    const float* mp = g_mean + ((size_t)b * MAXE + e) * F_;
    ms[t]       = mp[t];
    ms[t + 128] = mp[t + 128];
    __syncthreads();

    float s = m1b[t];
    for (int k = 0; k < F_; k++) s += ms[k] * m1w[k * H1_ + t];
    h1[t] = fmaxf(s, 0.f);
    __syncthreads();

    if (t < H2_) {
        float s2 = m2b[t];
        for (int k = 0; k < H1_; k++) s2 += h1[k] * m2w[k * H2_ + t];
        h2[t] = fmaxf(s2, 0.f);
    }
    __syncthreads();

    float p = (t < H2_) ? h2[t] * m3w[t] : 0.f;
#pragma unroll
    for (int off = 16; off; off >>= 1)
        p += __shfl_xor_sync(0xffffffffu, p, off);
    if ((t & 31) == 0) red[t >> 5] = p;
    __syncthreads();
    if (t == 0)
        g_ctx[b * MAXE + e] = red[0] + red[1] + red[2] + red[3] + m3b[0];
}

// grid (N, B), 256 threads: compat + adaptive weights -> out[..., 0:E]
__global__ __launch_bounds__(256)
void aw_kernel(const float* __restrict__ x, const int* __restrict__ Hm,
               const float* __restrict__ cw, const float* __restrict__ cb,
               const float* __restrict__ hb, const float* __restrict__ alpha,
               float* __restrict__ out)
{
    const int n = blockIdx.x, b = blockIdx.y, t = threadIdx.x;
    __shared__ float red[8];
    __shared__ float compat_s;

    float p = x[((size_t)b * N_ + n) * F_ + t] * cw[t];
#pragma unroll
    for (int off = 16; off; off >>= 1)
        p += __shfl_xor_sync(0xffffffffu, p, off);
    if ((t & 31) == 0) red[t >> 5] = p;
    __syncthreads();
    if (t == 0) {
        float s = 0.f;
#pragma unroll
        for (int i = 0; i < 8; i++) s += red[i];
        compat_s = s + cb[0] + hb[0];
    }
    __syncthreads();

    float val = 0.f;
    if (t < MAXE) {
        if (Hm[(size_t)n * E_ + t] && g_deg[t] > 1.0f) {
            float z = compat_s + alpha[0] * g_ctx[b * MAXE + t];
            val = 1.f / (1.f + __expf(-z));
        }
    }
    out[((size_t)b * N_ + n) * OUTC + t] = val;
}

// ---------------------------------------------------------------------------
// Launch
// ---------------------------------------------------------------------------
extern "C" void kernel_launch(void* const* d_in, const int* in_sizes, int n_in,
                              void* d_out, int out_size)
{
    const float* x      = (const float*)d_in[0];
    const int*   Hm     = (const int*)  d_in[1];
    const float* weight = (const float*)d_in[2];
    const float* bias   = (const float*)d_in[3];
    const float* Wn_w   = (const float*)d_in[4];
    const float* Wn_b   = (const float*)d_in[5];
    const float* m1_w   = (const float*)d_in[6];
    const float* m1_b   = (const float*)d_in[7];
    const float* m2_w   = (const float*)d_in[8];
    const float* m2_b   = (const float*)d_in[9];
    const float* m3_w   = (const float*)d_in[10];
    const float* m3_b   = (const float*)d_in[11];
    const float* c_w    = (const float*)d_in[12];
    const float* c_b    = (const float*)d_in[13];
    const float* hedgeb = (const float*)d_in[14];
    const float* alpha  = (const float*)d_in[15];
    float* out = (float*)d_out;

    float *xp, *v, *S;
    cudaGetSymbolAddress((void**)&xp, g_xp);
    cudaGetSymbolAddress((void**)&v,  g_v);
    cudaGetSymbolAddress((void**)&S,  g_S);

    // ---- hyperedge branch ----
    edge_mean_kernel<<<dim3(MAXE, B_), 256>>>(x, Hm);
    ctx_kernel<<<dim3(MAXE, B_), 128>>>(m1_w, m1_b, m2_w, m2_b, m3_w, m3_b);
    aw_kernel<<<dim3(N_, B_), 256>>>(x, Hm, c_w, c_b, hedgeb, alpha, out);

    // ---- projections: xp = x@Wn_w + Wn_b ; V = x@weight ----
    // treat x as [B*N, F]
    sgemm_nn<<<dim3(F_ / BN, (B_ * N_) / BM, 1), 256>>>(
        x, Wn_w, Wn_b, xp,
        B_ * N_, F_, F_, F_, F_, F_,
        (size_t)0, (size_t)0, (size_t)0, 1.0f);
    sgemm_nn<<<dim3(F_ / BN, (B_ * N_) / BM, 1), 256>>>(
        x, weight, nullptr, v,
        B_ * N_, F_, F_, F_, F_, F_,
        (size_t)0, (size_t)0, (size_t)0, 1.0f);

    // ---- S = xp @ xp^T / 16 (all batches via blockIdx.z) ----
    sgemm_nt<<<dim3(N_ / BN, N_ / BM, B_), 256>>>(
        xp, xp, S,
        N_, N_, F_, F_, F_, N_,
        (size_t)N_ * F_, (size_t)N_ * F_, (size_t)N_ * N_, 0.0625f);

    // ---- softmax rows ----
    softmax_rows<<<dim3(N_, 1, B_), 256>>>(S);

    // ---- y = softmax(S) @ V + bias -> out[..., E:E+F] ----
    sgemm_nn<<<dim3(F_ / BN, N_ / BM, B_), 256>>>(
        S, v, bias, out + E_,
        N_, F_, N_, N_, F_, OUTC,
        (size_t)N_ * N_, (size_t)N_ * F_, (size_t)N_ * OUTC, 1.0f);
}